// round 11
// baseline (speedup 1.0000x reference)
#include <cuda_runtime.h>
#include <cstdint>

// Problem constants
#define Bb   2
#define Nn   2048
#define Dd   1024
#define Hh   16
#define HALFW 64
#define QKV_COLS (3*Dd)   // 3072
#define Mrows (Bb*Nn)     // 4096

// Scratch (device globals; no allocation allowed)
__device__ float g_qkv[(size_t)Mrows*QKV_COLS];
__device__ float g_att[(size_t)Mrows*Dd];

// ---------------------------------------------------------------------------
__device__ __forceinline__ uint32_t smem_u32(const void* p) {
    uint32_t a;
    asm("{ .reg .u64 t; cvta.to.shared.u64 t, %1; cvt.u32.u64 %0, t; }"
        : "=r"(a) : "l"(p));
    return a;
}
__device__ __forceinline__ float rna_tf32(float x) {
    float r; asm("cvt.rna.tf32.f32 %0, %1;" : "=f"(r) : "f"(x)); return r;
}
__device__ __forceinline__ uint32_t rna_u32(uint32_t x) {
    float r; asm("cvt.rna.tf32.f32 %0, %1;" : "=f"(r) : "f"(__uint_as_float(x)));
    return __float_as_uint(r);
}
#define MMA_TF32(d0,d1,d2,d3, a0,a1,a2,a3, b0,b1) \
    asm volatile( \
        "mma.sync.aligned.m16n8k8.row.col.f32.tf32.tf32.f32 " \
        "{%0,%1,%2,%3}, {%4,%5,%6,%7}, {%8,%9}, {%0,%1,%2,%3};" \
        : "+f"(d0), "+f"(d1), "+f"(d2), "+f"(d3) \
        : "r"(a0), "r"(a1), "r"(a2), "r"(a3), "r"(b0), "r"(b1))

// ---------------------------------------------------------------------------
// tf32 mma.sync GEMM v3: C[M,N] = A[M,K] @ W[K,N] + bias[N]
// BM=BN=128, BK=32, 3-stage cp.async, 512 threads (16 warps, 4x4 grid of
// 32x32 warp tiles => 4 warps/SMSP for latency hiding).
// ROUND_A/ROUND_B: apply cvt.rna.tf32 to fragments in-kernel (fuses pre-pass).
// ---------------------------------------------------------------------------
#define BM 128
#define BN 128
#define BK 32
#define STAGES 3
#define ASTR 36
#define BSTR 136
#define STAGE_FLOATS (BM*ASTR + BK*BSTR)   // 8960
#define GEMM_SMEM (STAGES*STAGE_FLOATS*4)  // 107520 B
#define GTHREADS 512

__device__ __forceinline__ void g_load_stage(uint32_t sbase,
                                             const float* __restrict__ A,
                                             const float* __restrict__ W,
                                             int m0, int n0, int k0,
                                             int N, int K, int tid)
{
    // A tile: 128 rows x 32 k (1024 float4 chunks)
#pragma unroll
    for (int i = 0; i < 2; i++) {
        int c  = tid + i * GTHREADS;
        int mm = c >> 3, ch = c & 7;
        uint32_t dst = sbase + (uint32_t)(mm * ASTR + ch * 4) * 4u;
        const float* src = A + (size_t)(m0 + mm) * K + k0 + ch * 4;
        asm volatile("cp.async.cg.shared.global [%0], [%1], 16;" :: "r"(dst), "l"(src));
    }
    // B tile: 32 k-rows x 128 n (1024 chunks)
    uint32_t bb = sbase + (uint32_t)(BM * ASTR) * 4u;
#pragma unroll
    for (int i = 0; i < 2; i++) {
        int c  = tid + i * GTHREADS;
        int kr = c >> 5, ch = c & 31;
        uint32_t dst = bb + (uint32_t)(kr * BSTR + ch * 4) * 4u;
        const float* src = W + (size_t)(k0 + kr) * N + n0 + ch * 4;
        asm volatile("cp.async.cg.shared.global [%0], [%1], 16;" :: "r"(dst), "l"(src));
    }
    asm volatile("cp.async.commit_group;" ::: "memory");
}

template<bool RNA_OUT, bool ROUND_A, bool ROUND_B>
__global__ __launch_bounds__(GTHREADS, 1)
void tf32_mma_gemm(const float* __restrict__ A, const float* __restrict__ W,
                   const float* __restrict__ bias, float* __restrict__ C,
                   int M, int N, int K)
{
    extern __shared__ float sm[];
    const int tid  = threadIdx.x;
    const int wid  = tid >> 5;
    const int lane = tid & 31;
    const int g    = lane >> 2;
    const int t4   = lane & 3;
    const int m0 = blockIdx.y * BM;
    const int n0 = blockIdx.x * BN;
    const int wm = (wid >> 2) * 32;      // warp M offset (0,32,64,96)
    const int wn = (wid & 3) * 32;       // warp N offset
    const uint32_t smb = smem_u32(sm);

    float acc[2][4][4];
#pragma unroll
    for (int i = 0; i < 2; i++)
#pragma unroll
        for (int j = 0; j < 4; j++)
#pragma unroll
            for (int q = 0; q < 4; q++) acc[i][j][q] = 0.f;

    const int NITER = K / BK;
#pragma unroll
    for (int s = 0; s < STAGES - 1; s++)
        g_load_stage(smb + (uint32_t)(s * STAGE_FLOATS) * 4u, A, W, m0, n0, s * BK, N, K, tid);

    for (int it = 0; it < NITER; it++) {
        asm volatile("cp.async.wait_group %0;" :: "n"(STAGES - 2) : "memory");
        __syncthreads();

        if (it + STAGES - 1 < NITER) {
            int ps = (it + STAGES - 1) % STAGES;
            g_load_stage(smb + (uint32_t)(ps * STAGE_FLOATS) * 4u, A, W,
                         m0, n0, (it + STAGES - 1) * BK, N, K, tid);
        }

        const float* As = sm + (it % STAGES) * STAGE_FLOATS;
        const float* Bs = As + BM * ASTR;
        const uint32_t* Au = (const uint32_t*)As;
        const uint32_t* Bu = (const uint32_t*)Bs;

#pragma unroll
        for (int kk = 0; kk < BK; kk += 8) {
            uint32_t a[2][4], b[4][2];
#pragma unroll
            for (int mt = 0; mt < 2; mt++) {
                int r = wm + mt * 16 + g;
                a[mt][0] = Au[r * ASTR + kk + t4];
                a[mt][1] = Au[(r + 8) * ASTR + kk + t4];
                a[mt][2] = Au[r * ASTR + kk + t4 + 4];
                a[mt][3] = Au[(r + 8) * ASTR + kk + t4 + 4];
                if (ROUND_A) {
#pragma unroll
                    for (int q = 0; q < 4; q++) a[mt][q] = rna_u32(a[mt][q]);
                }
            }
#pragma unroll
            for (int nt = 0; nt < 4; nt++) {
                int cn = wn + nt * 8 + g;
                b[nt][0] = Bu[(kk + t4) * BSTR + cn];
                b[nt][1] = Bu[(kk + t4 + 4) * BSTR + cn];
                if (ROUND_B) {
                    b[nt][0] = rna_u32(b[nt][0]);
                    b[nt][1] = rna_u32(b[nt][1]);
                }
            }
#pragma unroll
            for (int nt = 0; nt < 4; nt++)
#pragma unroll
                for (int mt = 0; mt < 2; mt++)
                    MMA_TF32(acc[mt][nt][0], acc[mt][nt][1], acc[mt][nt][2], acc[mt][nt][3],
                             a[mt][0], a[mt][1], a[mt][2], a[mt][3], b[nt][0], b[nt][1]);
        }
    }

    // Epilogue: direct float2 stores with bias
#pragma unroll
    for (int nt = 0; nt < 4; nt++) {
        int cc = n0 + wn + nt * 8 + 2 * t4;
        float2 bv = *(const float2*)(bias + cc);
#pragma unroll
        for (int mt = 0; mt < 2; mt++) {
            int r0 = m0 + wm + mt * 16 + g;
            float2 o0, o1;
            o0.x = acc[mt][nt][0] + bv.x;  o0.y = acc[mt][nt][1] + bv.y;
            o1.x = acc[mt][nt][2] + bv.x;  o1.y = acc[mt][nt][3] + bv.y;
            if (RNA_OUT) {
                o0.x = rna_tf32(o0.x); o0.y = rna_tf32(o0.y);
                o1.x = rna_tf32(o1.x); o1.y = rna_tf32(o1.y);
            }
            *(float2*)(C + (size_t)r0 * N + cc)       = o0;
            *(float2*)(C + (size_t)(r0 + 8) * N + cc) = o1;
        }
    }
}

// ---------------------------------------------------------------------------
// Tensor-core local attention (round-10 version; known-good).
// ---------------------------------------------------------------------------
#define QT_STR 72
#define KS_STR 68
#define VS_STR 72
#define ST_STR 65
#define P_STR  196
#define QT_OFF 0
#define KS_OFF (64*QT_STR)
#define VS_OFF (KS_OFF + 192*KS_STR)
#define ST_OFF (VS_OFF + 192*VS_STR)
#define P_OFF  KS_OFF
#define ATT_FLOATS (ST_OFF + 192*ST_STR)
#define ATT_SMEM (ATT_FLOATS*4)

__global__ __launch_bounds__(256, 1)
void local_attn_mma(const float* __restrict__ qkv, float* __restrict__ out)
{
    extern __shared__ float sm[];
    float* Qt = sm + QT_OFF;
    float* Ks = sm + KS_OFF;
    float* Vs = sm + VS_OFF;
    float* St = sm + ST_OFF;
    float* Pp = sm + P_OFF;

    const int tid  = threadIdx.x;
    const int wid  = tid >> 5;
    const int lane = tid & 31;
    const int g    = lane >> 2;
    const int t4   = lane & 3;
    const int bh = blockIdx.y;
    const int b  = bh / Hh;
    const int h  = bh % Hh;
    const int q0 = blockIdx.x * 64;
    const int k0 = q0 - HALFW;
    const float* base = qkv + (size_t)b * Nn * QKV_COLS + h * 64;
    const uint32_t smb = smem_u32(sm);

#pragma unroll
    for (int i = 0; i < 12; i++) {
        int c   = tid + i * 256;
        int row = c >> 4;
        int ch  = c & 15;
        int t   = k0 + row;
        int tc  = t < 0 ? 0 : (t >= Nn ? Nn - 1 : t);
        int sz  = (t >= 0 && t < Nn) ? 16 : 0;
        const float* srck = base + (size_t)tc * QKV_COLS + Dd + ch * 4;
        const float* srcv = srck + Dd;
        uint32_t dk = smb + (uint32_t)(KS_OFF + row * KS_STR) * 4u + ch * 16;
        uint32_t dv = smb + (uint32_t)(VS_OFF + row * VS_STR) * 4u + ch * 16;
        asm volatile("cp.async.cg.shared.global [%0], [%1], 16, %2;"
                     :: "r"(dk), "l"(srck), "r"(sz));
        asm volatile("cp.async.cg.shared.global [%0], [%1], 16, %2;"
                     :: "r"(dv), "l"(srcv), "r"(sz));
    }
    asm volatile("cp.async.commit_group;" ::: "memory");

#pragma unroll
    for (int i = 0; i < 8; i++) {
        int qi = wid + i * 8;
        const float* rp = base + (size_t)(q0 + qi) * QKV_COLS;
        float v0 = rp[lane];
        float v1 = rp[lane + 32];
        Qt[lane * QT_STR + qi]        = v0;
        Qt[(lane + 32) * QT_STR + qi] = v1;
    }
    asm volatile("cp.async.wait_group 0;" ::: "memory");
    __syncthreads();

    {
        const int wmJ = (wid >> 1) * 48;
        const int wnQ = (wid & 1) * 32;
        const uint32_t* Ku = (const uint32_t*)Ks;
        const uint32_t* Qu = (const uint32_t*)Qt;
        float s[3][4][4];
#pragma unroll
        for (int i = 0; i < 3; i++)
#pragma unroll
            for (int j = 0; j < 4; j++)
#pragma unroll
                for (int q = 0; q < 4; q++) s[i][j][q] = 0.f;

#pragma unroll
        for (int kk = 0; kk < 64; kk += 8) {
            uint32_t a[3][4], bfr[4][2];
#pragma unroll
            for (int mt = 0; mt < 3; mt++) {
                int r = wmJ + mt * 16 + g;
                a[mt][0] = Ku[r * KS_STR + kk + t4];
                a[mt][1] = Ku[(r + 8) * KS_STR + kk + t4];
                a[mt][2] = Ku[r * KS_STR + kk + t4 + 4];
                a[mt][3] = Ku[(r + 8) * KS_STR + kk + t4 + 4];
            }
#pragma unroll
            for (int nt = 0; nt < 4; nt++) {
                int cn = wnQ + nt * 8 + g;
                bfr[nt][0] = Qu[(kk + t4) * QT_STR + cn];
                bfr[nt][1] = Qu[(kk + t4 + 4) * QT_STR + cn];
            }
#pragma unroll
            for (int mt = 0; mt < 3; mt++)
#pragma unroll
                for (int nt = 0; nt < 4; nt++)
                    MMA_TF32(s[mt][nt][0], s[mt][nt][1], s[mt][nt][2], s[mt][nt][3],
                             a[mt][0], a[mt][1], a[mt][2], a[mt][3],
                             bfr[nt][0], bfr[nt][1]);
        }

        const float scale = 0.125f;
#pragma unroll
        for (int mt = 0; mt < 3; mt++) {
#pragma unroll
            for (int nt = 0; nt < 4; nt++) {
                int qi0 = wnQ + nt * 8 + 2 * t4;
#pragma unroll
                for (int half = 0; half < 2; half++) {
                    int j = wmJ + mt * 16 + g + half * 8;
                    int t = k0 + j;
                    bool tin = (t >= 0) && (t < Nn);
                    float v0 = s[mt][nt][2 * half + 0];
                    float v1 = s[mt][nt][2 * half + 1];
                    bool ok0 = (j >= qi0) && (j <= qi0 + 2 * HALFW) && tin;
                    bool ok1 = (j >= qi0 + 1) && (j <= qi0 + 1 + 2 * HALFW) && tin;
                    St[j * ST_STR + qi0]     = ok0 ? v0 * scale : -1e30f;
                    St[j * ST_STR + qi0 + 1] = ok1 ? v1 * scale : -1e30f;
                }
            }
        }
    }
    __syncthreads();

#pragma unroll
    for (int i = 0; i < 8; i++) {
        int qi = wid * 8 + i;
        float v[6];
#pragma unroll
        for (int jj = 0; jj < 6; jj++)
            v[jj] = St[(lane + 32 * jj) * ST_STR + qi];
        float m = v[0];
#pragma unroll
        for (int jj = 1; jj < 6; jj++) m = fmaxf(m, v[jj]);
#pragma unroll
        for (int o = 16; o > 0; o >>= 1) m = fmaxf(m, __shfl_xor_sync(0xffffffffu, m, o));
        float e[6], ssum = 0.f;
#pragma unroll
        for (int jj = 0; jj < 6; jj++) { e[jj] = __expf(v[jj] - m); ssum += e[jj]; }
#pragma unroll
        for (int o = 16; o > 0; o >>= 1) ssum += __shfl_xor_sync(0xffffffffu, ssum, o);
        float inv = 1.f / ssum;
#pragma unroll
        for (int jj = 0; jj < 6; jj++)
            Pp[qi * P_STR + lane + 32 * jj] = rna_tf32(e[jj] * inv);
    }
    __syncthreads();

    {
        const int wm = (wid >> 1) * 16;
        const int wn = (wid & 1) * 32;
        const uint32_t* Pu = (const uint32_t*)Pp;
        const uint32_t* Vu = (const uint32_t*)Vs;
        float o[4][4];
#pragma unroll
        for (int i = 0; i < 4; i++)
#pragma unroll
            for (int q = 0; q < 4; q++) o[i][q] = 0.f;

#pragma unroll 4
        for (int kk = 0; kk < 192; kk += 8) {
            uint32_t a[4], bfr[4][2];
            int r = wm + g;
            a[0] = Pu[r * P_STR + kk + t4];
            a[1] = Pu[(r + 8) * P_STR + kk + t4];
            a[2] = Pu[r * P_STR + kk + t4 + 4];
            a[3] = Pu[(r + 8) * P_STR + kk + t4 + 4];
#pragma unroll
            for (int nt = 0; nt < 4; nt++) {
                int cn = wn + nt * 8 + g;
                bfr[nt][0] = Vu[(kk + t4) * VS_STR + cn];
                bfr[nt][1] = Vu[(kk + t4 + 4) * VS_STR + cn];
            }
#pragma unroll
            for (int nt = 0; nt < 4; nt++)
                MMA_TF32(o[nt][0], o[nt][1], o[nt][2], o[nt][3],
                         a[0], a[1], a[2], a[3], bfr[nt][0], bfr[nt][1]);
        }

#pragma unroll
        for (int nt = 0; nt < 4; nt++) {
            int d = wn + nt * 8 + 2 * t4;
#pragma unroll
            for (int half = 0; half < 2; half++) {
                int qi = wm + g + half * 8;
                float2 ov;
                ov.x = rna_tf32(o[nt][2 * half + 0]);
                ov.y = rna_tf32(o[nt][2 * half + 1]);
                *(float2*)(out + (size_t)(b * Nn + q0 + qi) * Dd + h * 64 + d) = ov;
            }
        }
    }
}

// ---------------------------------------------------------------------------
extern "C" void kernel_launch(void* const* d_in, const int* in_sizes, int n_in,
                              void* d_out, int out_size)
{
    const float* x    = (const float*)d_in[0];
    const float* Wqkv = (const float*)d_in[1];
    const float* bqkv = (const float*)d_in[2];
    const float* Wout = (const float*)d_in[3];
    const float* bout = (const float*)d_in[4];
    float* out = (float*)d_out;

    float *qkv, *att;
    cudaGetSymbolAddress((void**)&qkv, g_qkv);
    cudaGetSymbolAddress((void**)&att, g_att);

    // 1) QKV projection: round A & B fragments in-kernel, rna epilogue
    {
        cudaFuncSetAttribute((const void*)tf32_mma_gemm<true, true, true>,
                             cudaFuncAttributeMaxDynamicSharedMemorySize, GEMM_SMEM);
        dim3 grid(QKV_COLS / BN, Mrows / BM);
        tf32_mma_gemm<true, true, true><<<grid, GTHREADS, GEMM_SMEM>>>(
            x, Wqkv, bqkv, qkv, Mrows, QKV_COLS, Dd);
    }

    // 2) Banded local attention (tensor tf32)
    {
        cudaFuncSetAttribute(local_attn_mma,
                             cudaFuncAttributeMaxDynamicSharedMemorySize, ATT_SMEM);
        dim3 grid(Nn / 64, Bb * Hh);
        local_attn_mma<<<grid, 256, ATT_SMEM>>>(qkv, att);
    }

    // 3) Output projection: A pre-rounded (attn epilogue), round B in-kernel
    {
        cudaFuncSetAttribute((const void*)tf32_mma_gemm<false, false, true>,
                             cudaFuncAttributeMaxDynamicSharedMemorySize, GEMM_SMEM);
        dim3 grid(Dd / BN, Mrows / BM);
        tf32_mma_gemm<false, false, true><<<grid, GTHREADS, GEMM_SMEM>>>(
            att, Wout, bout, out, Mrows, Dd, Dd);
    }
}

// round 12
// speedup vs baseline: 1.2679x; 1.2679x over previous
#include <cuda_runtime.h>
#include <cstdint>

// Problem constants
#define Bb   2
#define Nn   2048
#define Dd   1024
#define Hh   16
#define HALFW 64
#define QKV_COLS (3*Dd)   // 3072
#define Mrows (Bb*Nn)     // 4096

// Scratch (device globals; no allocation allowed)
__device__ float g_qkv[(size_t)Mrows*QKV_COLS];
__device__ float g_att[(size_t)Mrows*Dd];

// ---------------------------------------------------------------------------
__device__ __forceinline__ uint32_t smem_u32(const void* p) {
    uint32_t a;
    asm("{ .reg .u64 t; cvta.to.shared.u64 t, %1; cvt.u32.u64 %0, t; }"
        : "=r"(a) : "l"(p));
    return a;
}
__device__ __forceinline__ float rna_tf32(float x) {
    float r; asm("cvt.rna.tf32.f32 %0, %1;" : "=f"(r) : "f"(x)); return r;
}
__device__ __forceinline__ uint32_t rna_u32(uint32_t x) {
    float r; asm("cvt.rna.tf32.f32 %0, %1;" : "=f"(r) : "f"(__uint_as_float(x)));
    return __float_as_uint(r);
}
#define MMA_TF32(d0,d1,d2,d3, a0,a1,a2,a3, b0,b1) \
    asm volatile( \
        "mma.sync.aligned.m16n8k8.row.col.f32.tf32.tf32.f32 " \
        "{%0,%1,%2,%3}, {%4,%5,%6,%7}, {%8,%9}, {%0,%1,%2,%3};" \
        : "+f"(d0), "+f"(d1), "+f"(d2), "+f"(d3) \
        : "r"(a0), "r"(a1), "r"(a2), "r"(a3), "r"(b0), "r"(b1))

// ---------------------------------------------------------------------------
// tf32 mma.sync GEMM (round-10 winning config: 128 threads, 4 warps, 64x64
// warp tiles, BK=32, 3-stage cp.async). ROUND_A/ROUND_B fuse tf32 rna
// rounding into the fragment loads (replaces the pre-pass kernels).
// ---------------------------------------------------------------------------
#define BM 128
#define BN 128
#define BK 32
#define STAGES 3
#define ASTR 36
#define BSTR 136
#define STAGE_FLOATS (BM*ASTR + BK*BSTR)   // 8960
#define GEMM_SMEM (STAGES*STAGE_FLOATS*4)  // 107520 B
#define GTHREADS 128

__device__ __forceinline__ void g_load_stage(uint32_t sbase,
                                             const float* __restrict__ A,
                                             const float* __restrict__ W,
                                             int m0, int n0, int k0,
                                             int N, int K, int tid)
{
#pragma unroll
    for (int i = 0; i < 8; i++) {
        int c  = tid + i * GTHREADS;
        int mm = c >> 3, ch = c & 7;
        uint32_t dst = sbase + (uint32_t)(mm * ASTR + ch * 4) * 4u;
        const float* src = A + (size_t)(m0 + mm) * K + k0 + ch * 4;
        asm volatile("cp.async.cg.shared.global [%0], [%1], 16;" :: "r"(dst), "l"(src));
    }
    uint32_t bb = sbase + (uint32_t)(BM * ASTR) * 4u;
#pragma unroll
    for (int i = 0; i < 8; i++) {
        int c  = tid + i * GTHREADS;
        int kr = c >> 5, ch = c & 31;
        uint32_t dst = bb + (uint32_t)(kr * BSTR + ch * 4) * 4u;
        const float* src = W + (size_t)(k0 + kr) * N + n0 + ch * 4;
        asm volatile("cp.async.cg.shared.global [%0], [%1], 16;" :: "r"(dst), "l"(src));
    }
    asm volatile("cp.async.commit_group;" ::: "memory");
}

template<bool RNA_OUT, bool ROUND_A, bool ROUND_B>
__global__ __launch_bounds__(GTHREADS, 2)
void tf32_mma_gemm(const float* __restrict__ A, const float* __restrict__ W,
                   const float* __restrict__ bias, float* __restrict__ C,
                   int M, int N, int K)
{
    extern __shared__ float sm[];
    const int tid  = threadIdx.x;
    const int wid  = tid >> 5;
    const int lane = tid & 31;
    const int g    = lane >> 2;
    const int t4   = lane & 3;
    const int m0 = blockIdx.y * BM;
    const int n0 = blockIdx.x * BN;
    const int wm = (wid >> 1) * 64;
    const int wn = (wid & 1) * 64;
    const uint32_t smb = smem_u32(sm);

    float acc[4][8][4];
#pragma unroll
    for (int i = 0; i < 4; i++)
#pragma unroll
        for (int j = 0; j < 8; j++)
#pragma unroll
            for (int q = 0; q < 4; q++) acc[i][j][q] = 0.f;

    const int NITER = K / BK;
#pragma unroll
    for (int s = 0; s < STAGES - 1; s++)
        g_load_stage(smb + (uint32_t)(s * STAGE_FLOATS) * 4u, A, W, m0, n0, s * BK, N, K, tid);

    for (int it = 0; it < NITER; it++) {
        asm volatile("cp.async.wait_group %0;" :: "n"(STAGES - 2) : "memory");
        __syncthreads();

        if (it + STAGES - 1 < NITER) {
            int ps = (it + STAGES - 1) % STAGES;
            g_load_stage(smb + (uint32_t)(ps * STAGE_FLOATS) * 4u, A, W,
                         m0, n0, (it + STAGES - 1) * BK, N, K, tid);
        }

        const float* As = sm + (it % STAGES) * STAGE_FLOATS;
        const float* Bs = As + BM * ASTR;
        const uint32_t* Au = (const uint32_t*)As;
        const uint32_t* Bu = (const uint32_t*)Bs;

#pragma unroll
        for (int kk = 0; kk < BK; kk += 8) {
            uint32_t a[4][4];
#pragma unroll
            for (int mt = 0; mt < 4; mt++) {
                int r = wm + mt * 16 + g;
                a[mt][0] = Au[r * ASTR + kk + t4];
                a[mt][1] = Au[(r + 8) * ASTR + kk + t4];
                a[mt][2] = Au[r * ASTR + kk + t4 + 4];
                a[mt][3] = Au[(r + 8) * ASTR + kk + t4 + 4];
                if (ROUND_A) {
#pragma unroll
                    for (int q = 0; q < 4; q++) a[mt][q] = rna_u32(a[mt][q]);
                }
            }
#pragma unroll
            for (int nt = 0; nt < 8; nt++) {
                int cn = wn + nt * 8 + g;
                uint32_t b0 = Bu[(kk + t4) * BSTR + cn];
                uint32_t b1 = Bu[(kk + t4 + 4) * BSTR + cn];
                if (ROUND_B) {
                    b0 = rna_u32(b0);
                    b1 = rna_u32(b1);
                }
#pragma unroll
                for (int mt = 0; mt < 4; mt++)
                    MMA_TF32(acc[mt][nt][0], acc[mt][nt][1], acc[mt][nt][2], acc[mt][nt][3],
                             a[mt][0], a[mt][1], a[mt][2], a[mt][3], b0, b1);
            }
        }
    }

#pragma unroll
    for (int nt = 0; nt < 8; nt++) {
        int cc = n0 + wn + nt * 8 + 2 * t4;
        float2 bv = *(const float2*)(bias + cc);
#pragma unroll
        for (int mt = 0; mt < 4; mt++) {
            int r0 = m0 + wm + mt * 16 + g;
            float2 o0, o1;
            o0.x = acc[mt][nt][0] + bv.x;  o0.y = acc[mt][nt][1] + bv.y;
            o1.x = acc[mt][nt][2] + bv.x;  o1.y = acc[mt][nt][3] + bv.y;
            if (RNA_OUT) {
                o0.x = rna_tf32(o0.x); o0.y = rna_tf32(o0.y);
                o1.x = rna_tf32(o1.x); o1.y = rna_tf32(o1.y);
            }
            *(float2*)(C + (size_t)r0 * N + cc)       = o0;
            *(float2*)(C + (size_t)(r0 + 8) * N + cc) = o1;
        }
    }
}

// ---------------------------------------------------------------------------
// Tensor-core local attention (round-10 version; known-good).
// ---------------------------------------------------------------------------
#define QT_STR 72
#define KS_STR 68
#define VS_STR 72
#define ST_STR 65
#define P_STR  196
#define QT_OFF 0
#define KS_OFF (64*QT_STR)
#define VS_OFF (KS_OFF + 192*KS_STR)
#define ST_OFF (VS_OFF + 192*VS_STR)
#define P_OFF  KS_OFF
#define ATT_FLOATS (ST_OFF + 192*ST_STR)
#define ATT_SMEM (ATT_FLOATS*4)

__global__ __launch_bounds__(256, 1)
void local_attn_mma(const float* __restrict__ qkv, float* __restrict__ out)
{
    extern __shared__ float sm[];
    float* Qt = sm + QT_OFF;
    float* Ks = sm + KS_OFF;
    float* Vs = sm + VS_OFF;
    float* St = sm + ST_OFF;
    float* Pp = sm + P_OFF;

    const int tid  = threadIdx.x;
    const int wid  = tid >> 5;
    const int lane = tid & 31;
    const int g    = lane >> 2;
    const int t4   = lane & 3;
    const int bh = blockIdx.y;
    const int b  = bh / Hh;
    const int h  = bh % Hh;
    const int q0 = blockIdx.x * 64;
    const int k0 = q0 - HALFW;
    const float* base = qkv + (size_t)b * Nn * QKV_COLS + h * 64;
    const uint32_t smb = smem_u32(sm);

#pragma unroll
    for (int i = 0; i < 12; i++) {
        int c   = tid + i * 256;
        int row = c >> 4;
        int ch  = c & 15;
        int t   = k0 + row;
        int tc  = t < 0 ? 0 : (t >= Nn ? Nn - 1 : t);
        int sz  = (t >= 0 && t < Nn) ? 16 : 0;
        const float* srck = base + (size_t)tc * QKV_COLS + Dd + ch * 4;
        const float* srcv = srck + Dd;
        uint32_t dk = smb + (uint32_t)(KS_OFF + row * KS_STR) * 4u + ch * 16;
        uint32_t dv = smb + (uint32_t)(VS_OFF + row * VS_STR) * 4u + ch * 16;
        asm volatile("cp.async.cg.shared.global [%0], [%1], 16, %2;"
                     :: "r"(dk), "l"(srck), "r"(sz));
        asm volatile("cp.async.cg.shared.global [%0], [%1], 16, %2;"
                     :: "r"(dv), "l"(srcv), "r"(sz));
    }
    asm volatile("cp.async.commit_group;" ::: "memory");

#pragma unroll
    for (int i = 0; i < 8; i++) {
        int qi = wid + i * 8;
        const float* rp = base + (size_t)(q0 + qi) * QKV_COLS;
        float v0 = rp[lane];
        float v1 = rp[lane + 32];
        Qt[lane * QT_STR + qi]        = v0;
        Qt[(lane + 32) * QT_STR + qi] = v1;
    }
    asm volatile("cp.async.wait_group 0;" ::: "memory");
    __syncthreads();

    {
        const int wmJ = (wid >> 1) * 48;
        const int wnQ = (wid & 1) * 32;
        const uint32_t* Ku = (const uint32_t*)Ks;
        const uint32_t* Qu = (const uint32_t*)Qt;
        float s[3][4][4];
#pragma unroll
        for (int i = 0; i < 3; i++)
#pragma unroll
            for (int j = 0; j < 4; j++)
#pragma unroll
                for (int q = 0; q < 4; q++) s[i][j][q] = 0.f;

#pragma unroll
        for (int kk = 0; kk < 64; kk += 8) {
            uint32_t a[3][4], bfr[4][2];
#pragma unroll
            for (int mt = 0; mt < 3; mt++) {
                int r = wmJ + mt * 16 + g;
                a[mt][0] = Ku[r * KS_STR + kk + t4];
                a[mt][1] = Ku[(r + 8) * KS_STR + kk + t4];
                a[mt][2] = Ku[r * KS_STR + kk + t4 + 4];
                a[mt][3] = Ku[(r + 8) * KS_STR + kk + t4 + 4];
            }
#pragma unroll
            for (int nt = 0; nt < 4; nt++) {
                int cn = wnQ + nt * 8 + g;
                bfr[nt][0] = Qu[(kk + t4) * QT_STR + cn];
                bfr[nt][1] = Qu[(kk + t4 + 4) * QT_STR + cn];
            }
#pragma unroll
            for (int mt = 0; mt < 3; mt++)
#pragma unroll
                for (int nt = 0; nt < 4; nt++)
                    MMA_TF32(s[mt][nt][0], s[mt][nt][1], s[mt][nt][2], s[mt][nt][3],
                             a[mt][0], a[mt][1], a[mt][2], a[mt][3],
                             bfr[nt][0], bfr[nt][1]);
        }

        const float scale = 0.125f;
#pragma unroll
        for (int mt = 0; mt < 3; mt++) {
#pragma unroll
            for (int nt = 0; nt < 4; nt++) {
                int qi0 = wnQ + nt * 8 + 2 * t4;
#pragma unroll
                for (int half = 0; half < 2; half++) {
                    int j = wmJ + mt * 16 + g + half * 8;
                    int t = k0 + j;
                    bool tin = (t >= 0) && (t < Nn);
                    float v0 = s[mt][nt][2 * half + 0];
                    float v1 = s[mt][nt][2 * half + 1];
                    bool ok0 = (j >= qi0) && (j <= qi0 + 2 * HALFW) && tin;
                    bool ok1 = (j >= qi0 + 1) && (j <= qi0 + 1 + 2 * HALFW) && tin;
                    St[j * ST_STR + qi0]     = ok0 ? v0 * scale : -1e30f;
                    St[j * ST_STR + qi0 + 1] = ok1 ? v1 * scale : -1e30f;
                }
            }
        }
    }
    __syncthreads();

#pragma unroll
    for (int i = 0; i < 8; i++) {
        int qi = wid * 8 + i;
        float v[6];
#pragma unroll
        for (int jj = 0; jj < 6; jj++)
            v[jj] = St[(lane + 32 * jj) * ST_STR + qi];
        float m = v[0];
#pragma unroll
        for (int jj = 1; jj < 6; jj++) m = fmaxf(m, v[jj]);
#pragma unroll
        for (int o = 16; o > 0; o >>= 1) m = fmaxf(m, __shfl_xor_sync(0xffffffffu, m, o));
        float e[6], ssum = 0.f;
#pragma unroll
        for (int jj = 0; jj < 6; jj++) { e[jj] = __expf(v[jj] - m); ssum += e[jj]; }
#pragma unroll
        for (int o = 16; o > 0; o >>= 1) ssum += __shfl_xor_sync(0xffffffffu, ssum, o);
        float inv = 1.f / ssum;
#pragma unroll
        for (int jj = 0; jj < 6; jj++)
            Pp[qi * P_STR + lane + 32 * jj] = rna_tf32(e[jj] * inv);
    }
    __syncthreads();

    {
        const int wm = (wid >> 1) * 16;
        const int wn = (wid & 1) * 32;
        const uint32_t* Pu = (const uint32_t*)Pp;
        const uint32_t* Vu = (const uint32_t*)Vs;
        float o[4][4];
#pragma unroll
        for (int i = 0; i < 4; i++)
#pragma unroll
            for (int q = 0; q < 4; q++) o[i][q] = 0.f;

#pragma unroll 4
        for (int kk = 0; kk < 192; kk += 8) {
            uint32_t a[4], bfr[4][2];
            int r = wm + g;
            a[0] = Pu[r * P_STR + kk + t4];
            a[1] = Pu[(r + 8) * P_STR + kk + t4];
            a[2] = Pu[r * P_STR + kk + t4 + 4];
            a[3] = Pu[(r + 8) * P_STR + kk + t4 + 4];
#pragma unroll
            for (int nt = 0; nt < 4; nt++) {
                int cn = wn + nt * 8 + g;
                bfr[nt][0] = Vu[(kk + t4) * VS_STR + cn];
                bfr[nt][1] = Vu[(kk + t4 + 4) * VS_STR + cn];
            }
#pragma unroll
            for (int nt = 0; nt < 4; nt++)
                MMA_TF32(o[nt][0], o[nt][1], o[nt][2], o[nt][3],
                         a[0], a[1], a[2], a[3], bfr[nt][0], bfr[nt][1]);
        }

#pragma unroll
        for (int nt = 0; nt < 4; nt++) {
            int d = wn + nt * 8 + 2 * t4;
#pragma unroll
            for (int half = 0; half < 2; half++) {
                int qi = wm + g + half * 8;
                float2 ov;
                ov.x = rna_tf32(o[nt][2 * half + 0]);
                ov.y = rna_tf32(o[nt][2 * half + 1]);
                *(float2*)(out + (size_t)(b * Nn + q0 + qi) * Dd + h * 64 + d) = ov;
            }
        }
    }
}

// ---------------------------------------------------------------------------
extern "C" void kernel_launch(void* const* d_in, const int* in_sizes, int n_in,
                              void* d_out, int out_size)
{
    const float* x    = (const float*)d_in[0];
    const float* Wqkv = (const float*)d_in[1];
    const float* bqkv = (const float*)d_in[2];
    const float* Wout = (const float*)d_in[3];
    const float* bout = (const float*)d_in[4];
    float* out = (float*)d_out;

    float *qkv, *att;
    cudaGetSymbolAddress((void**)&qkv, g_qkv);
    cudaGetSymbolAddress((void**)&att, g_att);

    // 1) QKV projection: round A & B fragments in-kernel, rna epilogue
    {
        cudaFuncSetAttribute((const void*)tf32_mma_gemm<true, true, true>,
                             cudaFuncAttributeMaxDynamicSharedMemorySize, GEMM_SMEM);
        dim3 grid(QKV_COLS / BN, Mrows / BM);
        tf32_mma_gemm<true, true, true><<<grid, GTHREADS, GEMM_SMEM>>>(
            x, Wqkv, bqkv, qkv, Mrows, QKV_COLS, Dd);
    }

    // 2) Banded local attention (tensor tf32)
    {
        cudaFuncSetAttribute(local_attn_mma,
                             cudaFuncAttributeMaxDynamicSharedMemorySize, ATT_SMEM);
        dim3 grid(Nn / 64, Bb * Hh);
        local_attn_mma<<<grid, 256, ATT_SMEM>>>(qkv, att);
    }

    // 3) Output projection: A pre-rounded (attn epilogue), round B in-kernel
    {
        cudaFuncSetAttribute((const void*)tf32_mma_gemm<false, false, true>,
                             cudaFuncAttributeMaxDynamicSharedMemorySize, GEMM_SMEM);
        dim3 grid(Dd / BN, Mrows / BM);
        tf32_mma_gemm<false, false, true><<<grid, GTHREADS, GEMM_SMEM>>>(
            att, Wout, bout, out, Mrows, Dd, Dd);
    }
}

// round 13
// speedup vs baseline: 2.2182x; 1.7495x over previous
#include <cuda_runtime.h>
#include <cuda_fp16.h>
#include <cstdint>

// Problem constants
#define Bb   2
#define Nn   2048
#define Dd   1024
#define Hh   16
#define HALFW 64
#define QKV_COLS (3*Dd)   // 3072
#define Mrows (Bb*Nn)     // 4096

// Scratch (device globals; no allocation allowed)
__device__ __half g_qkv[(size_t)Mrows*QKV_COLS];   // fp16 qkv
__device__ __half g_att[(size_t)Mrows*Dd];         // fp16 attention output
__device__ __half g_xh [(size_t)Mrows*Dd];         // x in fp16
__device__ __half g_W1t[(size_t)QKV_COLS*Dd];      // Wqkv^T fp16 [N][K]
__device__ __half g_W2t[(size_t)Dd*Dd];            // Wout^T fp16 [N][K]

// ---------------------------------------------------------------------------
__device__ __forceinline__ uint32_t smem_u32(const void* p) {
    uint32_t a;
    asm("{ .reg .u64 t; cvta.to.shared.u64 t, %1; cvt.u32.u64 %0, t; }"
        : "=r"(a) : "l"(p));
    return a;
}
#define MMA_F16(d0,d1,d2,d3, a0,a1,a2,a3, b0,b1) \
    asm volatile( \
        "mma.sync.aligned.m16n8k16.row.col.f32.f16.f16.f32 " \
        "{%0,%1,%2,%3}, {%4,%5,%6,%7}, {%8,%9}, {%0,%1,%2,%3};" \
        : "+f"(d0), "+f"(d1), "+f"(d2), "+f"(d3) \
        : "r"(a0), "r"(a1), "r"(a2), "r"(a3), "r"(b0), "r"(b1))

// ---------------------------------------------------------------------------
// fp16 mma.sync GEMM: C[M,N] = A[M,K] @ Bt[N,K]^T + bias[N]
// A: [M][K] fp16 row-major. Bt: [N][K] fp16 (pre-transposed).
// BM=BN=128, BK=64 halves, 3-stage cp.async, 128 threads, 4 warps 64x64.
// Smem rows: 64 data halves + 8 pad = 72 halves = 36 words (≡4 mod 32:
// conflict-free fragment loads for both operands).
// ---------------------------------------------------------------------------
#define BM 128
#define BN 128
#define BKH 64
#define STAGES 3
#define SWW 36                                // words per smem row
#define ROWB (SWW*4)                          // 144 bytes per row
#define STAGE_BYTES (2*BM*ROWB)               // A + B = 36864
#define GEMM_SMEM (STAGES*STAGE_BYTES)        // 110592
#define GTHREADS 128

__device__ __forceinline__ void g_load_stage(uint32_t sbase,
                                             const __half* __restrict__ A,
                                             const __half* __restrict__ Bt,
                                             int m0, int n0, int k0,
                                             int K, int tid)
{
#pragma unroll
    for (int i = 0; i < 8; i++) {
        int c  = tid + i * GTHREADS;          // 0..1023
        int row = c >> 3, ch = c & 7;
        uint32_t dst = sbase + (uint32_t)(row * ROWB + ch * 16);
        const __half* src = A + (size_t)(m0 + row) * K + k0 + ch * 8;
        asm volatile("cp.async.cg.shared.global [%0], [%1], 16;" :: "r"(dst), "l"(src));
    }
    uint32_t bb = sbase + (uint32_t)(BM * ROWB);
#pragma unroll
    for (int i = 0; i < 8; i++) {
        int c  = tid + i * GTHREADS;
        int row = c >> 3, ch = c & 7;
        uint32_t dst = bb + (uint32_t)(row * ROWB + ch * 16);
        const __half* src = Bt + (size_t)(n0 + row) * K + k0 + ch * 8;
        asm volatile("cp.async.cg.shared.global [%0], [%1], 16;" :: "r"(dst), "l"(src));
    }
    asm volatile("cp.async.commit_group;" ::: "memory");
}

template<bool HALF_OUT>
__global__ __launch_bounds__(GTHREADS, 2)
void f16_mma_gemm(const __half* __restrict__ A, const __half* __restrict__ Bt,
                  const float* __restrict__ bias, void* __restrict__ Cv,
                  int M, int N, int K)
{
    extern __shared__ char smc[];
    const int tid  = threadIdx.x;
    const int wid  = tid >> 5;
    const int lane = tid & 31;
    const int g    = lane >> 2;
    const int t4   = lane & 3;
    const int m0 = blockIdx.y * BM;
    const int n0 = blockIdx.x * BN;
    const int wm = (wid >> 1) * 64;
    const int wn = (wid & 1) * 64;
    const uint32_t smb = smem_u32(smc);

    float acc[4][8][4];
#pragma unroll
    for (int i = 0; i < 4; i++)
#pragma unroll
        for (int j = 0; j < 8; j++)
#pragma unroll
            for (int q = 0; q < 4; q++) acc[i][j][q] = 0.f;

    const int NITER = K / BKH;                // 16
#pragma unroll
    for (int s = 0; s < STAGES - 1; s++)
        g_load_stage(smb + (uint32_t)(s * STAGE_BYTES), A, Bt, m0, n0, s * BKH, K, tid);

    for (int it = 0; it < NITER; it++) {
        asm volatile("cp.async.wait_group %0;" :: "n"(STAGES - 2) : "memory");
        __syncthreads();

        if (it + STAGES - 1 < NITER) {
            int ps = (it + STAGES - 1) % STAGES;
            g_load_stage(smb + (uint32_t)(ps * STAGE_BYTES), A, Bt,
                         m0, n0, (it + STAGES - 1) * BKH, K, tid);
        }

        const uint32_t* Au = (const uint32_t*)(smc + (it % STAGES) * STAGE_BYTES);
        const uint32_t* Bu = Au + BM * SWW;

#pragma unroll
        for (int ks = 0; ks < 4; ks++) {      // k16 steps; kw in words
            const int kw = ks * 8;
            uint32_t a[4][4];
#pragma unroll
            for (int mt = 0; mt < 4; mt++) {
                int r = wm + mt * 16 + g;
                a[mt][0] = Au[r * SWW + t4 + kw];
                a[mt][1] = Au[(r + 8) * SWW + t4 + kw];
                a[mt][2] = Au[r * SWW + t4 + 4 + kw];
                a[mt][3] = Au[(r + 8) * SWW + t4 + 4 + kw];
            }
#pragma unroll
            for (int nt = 0; nt < 8; nt++) {
                int cn = wn + nt * 8 + g;
                uint32_t b0 = Bu[cn * SWW + t4 + kw];
                uint32_t b1 = Bu[cn * SWW + t4 + 4 + kw];
#pragma unroll
                for (int mt = 0; mt < 4; mt++)
                    MMA_F16(acc[mt][nt][0], acc[mt][nt][1], acc[mt][nt][2], acc[mt][nt][3],
                            a[mt][0], a[mt][1], a[mt][2], a[mt][3], b0, b1);
            }
        }
    }

#pragma unroll
    for (int nt = 0; nt < 8; nt++) {
        int cc = n0 + wn + nt * 8 + 2 * t4;
        float2 bv = *(const float2*)(bias + cc);
#pragma unroll
        for (int mt = 0; mt < 4; mt++) {
            int r0 = m0 + wm + mt * 16 + g;
            float2 o0, o1;
            o0.x = acc[mt][nt][0] + bv.x;  o0.y = acc[mt][nt][1] + bv.y;
            o1.x = acc[mt][nt][2] + bv.x;  o1.y = acc[mt][nt][3] + bv.y;
            if (HALF_OUT) {
                __half* Ch = (__half*)Cv;
                *(__half2*)(Ch + (size_t)r0 * N + cc)       = __floats2half2_rn(o0.x, o0.y);
                *(__half2*)(Ch + (size_t)(r0 + 8) * N + cc) = __floats2half2_rn(o1.x, o1.y);
            } else {
                float* Cf = (float*)Cv;
                *(float2*)(Cf + (size_t)r0 * N + cc)       = o0;
                *(float2*)(Cf + (size_t)(r0 + 8) * N + cc) = o1;
            }
        }
    }
}

// ---------------------------------------------------------------------------
// Pre-passes: fp32 -> fp16 convert; transpose+convert for weights.
// ---------------------------------------------------------------------------
__global__ void cvt_f16_kernel(const float* __restrict__ in, __half* __restrict__ out, int n4)
{
    int i = blockIdx.x * blockDim.x + threadIdx.x;
    if (i < n4) {
        float4 v = ((const float4*)in)[i];
        __half2 h0 = __floats2half2_rn(v.x, v.y);
        __half2 h1 = __floats2half2_rn(v.z, v.w);
        uint2 u;
        u.x = *(uint32_t*)&h0;
        u.y = *(uint32_t*)&h1;
        ((uint2*)out)[i] = u;
    }
}

// W [K][N] fp32 -> WT [N][K] fp16
__global__ void transpose_cvt_kernel(const float* __restrict__ W, __half* __restrict__ WT,
                                     int K, int N)
{
    __shared__ float t[32][33];
    int x = blockIdx.x * 32 + threadIdx.x;                 // n
#pragma unroll
    for (int j = 0; j < 4; j++) {
        int y = blockIdx.y * 32 + threadIdx.y + j * 8;     // k
        t[threadIdx.y + j * 8][threadIdx.x] = W[(size_t)y * N + x];
    }
    __syncthreads();
    int x2 = blockIdx.y * 32 + threadIdx.x;                // k
#pragma unroll
    for (int j = 0; j < 4; j++) {
        int y2 = blockIdx.x * 32 + threadIdx.y + j * 8;    // n
        WT[(size_t)y2 * K + x2] = __float2half_rn(t[threadIdx.x][threadIdx.y + j * 8]);
    }
}

// ---------------------------------------------------------------------------
// fp16 tensor-core local attention.
// Qs[qi][72h] (B-operand: row-major == col-major k layout), Ks[j][72h],
// Vs[j][72h], St fp32 [j][65], P fp16 [qi][200h] overlays Ks.
// ---------------------------------------------------------------------------
#define AQ_OFF 0
#define AK_OFF 9216                       // 64*144
#define AV_OFF (AK_OFF + 192*144)         // 36864
#define AST_OFF (AV_OFF + 192*144)        // 64512
#define AP_OFF AK_OFF                     // P (64*200*2=25600B) <= Ks (27648B)
#define AST_STR 65
#define PSW 100                           // P words per row (200 halves)
#define ATT_SMEM (AST_OFF + 192*AST_STR*4)   // 114432 B

__global__ __launch_bounds__(256, 2)
void local_attn_f16(const __half* __restrict__ qkv, __half* __restrict__ out)
{
    extern __shared__ char smc[];
    __half* Vs = (__half*)(smc + AV_OFF);
    float*  St = (float*)(smc + AST_OFF);
    __half* Pp = (__half*)(smc + AP_OFF);

    const int tid  = threadIdx.x;
    const int wid  = tid >> 5;
    const int lane = tid & 31;
    const int g    = lane >> 2;
    const int t4   = lane & 3;
    const int bh = blockIdx.y;
    const int b  = bh / Hh;
    const int h  = bh % Hh;
    const int q0 = blockIdx.x * 64;
    const int k0 = q0 - HALFW;
    const __half* base = qkv + (size_t)b * Nn * QKV_COLS + h * 64;
    const uint32_t smb = smem_u32(smc);

    // --- K,V via cp.async (192 rows x 8 chunks each; zero-fill OOB) ---
#pragma unroll
    for (int i = 0; i < 6; i++) {
        int c   = tid + i * 256;              // 0..1535
        int row = c >> 3, ch = c & 7;
        int t   = k0 + row;
        int tc  = t < 0 ? 0 : (t >= Nn ? Nn - 1 : t);
        int sz  = (t >= 0 && t < Nn) ? 16 : 0;
        const __half* srck = base + (size_t)tc * QKV_COLS + Dd + ch * 8;
        const __half* srcv = srck + Dd;
        uint32_t dk = smb + (uint32_t)(AK_OFF + row * 144 + ch * 16);
        uint32_t dv = smb + (uint32_t)(AV_OFF + row * 144 + ch * 16);
        asm volatile("cp.async.cg.shared.global [%0], [%1], 16, %2;"
                     :: "r"(dk), "l"(srck), "r"(sz));
        asm volatile("cp.async.cg.shared.global [%0], [%1], 16, %2;"
                     :: "r"(dv), "l"(srcv), "r"(sz));
    }
    // --- Q (64 rows x 8 chunks) ---
#pragma unroll
    for (int i = 0; i < 2; i++) {
        int c   = tid + i * 256;              // 0..511
        int row = c >> 3, ch = c & 7;
        const __half* src = base + (size_t)(q0 + row) * QKV_COLS + ch * 8;
        uint32_t dq = smb + (uint32_t)(AQ_OFF + row * 144 + ch * 16);
        asm volatile("cp.async.cg.shared.global [%0], [%1], 16;" :: "r"(dq), "l"(src));
    }
    asm volatile("cp.async.commit_group;" ::: "memory");
    asm volatile("cp.async.wait_group 0;" ::: "memory");
    __syncthreads();

    // --- scores (transposed): St[j][qi] = K·Q^T ; warp grid 4(j) x 2(qi) ---
    {
        const int wmJ = (wid >> 1) * 48;
        const int wnQ = (wid & 1) * 32;
        const uint32_t* Ku = (const uint32_t*)(smc + AK_OFF);
        const uint32_t* Qu = (const uint32_t*)(smc + AQ_OFF);
        float s[3][4][4];
#pragma unroll
        for (int i = 0; i < 3; i++)
#pragma unroll
            for (int j = 0; j < 4; j++)
#pragma unroll
                for (int q = 0; q < 4; q++) s[i][j][q] = 0.f;

#pragma unroll
        for (int ks = 0; ks < 4; ks++) {      // d = 64 halves, 4 k16-steps
            const int kw = ks * 8;
            uint32_t a[3][4], bfr[4][2];
#pragma unroll
            for (int mt = 0; mt < 3; mt++) {
                int r = wmJ + mt * 16 + g;
                a[mt][0] = Ku[r * 36 + t4 + kw];
                a[mt][1] = Ku[(r + 8) * 36 + t4 + kw];
                a[mt][2] = Ku[r * 36 + t4 + 4 + kw];
                a[mt][3] = Ku[(r + 8) * 36 + t4 + 4 + kw];
            }
#pragma unroll
            for (int nt = 0; nt < 4; nt++) {
                int cn = wnQ + nt * 8 + g;
                bfr[nt][0] = Qu[cn * 36 + t4 + kw];
                bfr[nt][1] = Qu[cn * 36 + t4 + 4 + kw];
            }
#pragma unroll
            for (int mt = 0; mt < 3; mt++)
#pragma unroll
                for (int nt = 0; nt < 4; nt++)
                    MMA_F16(s[mt][nt][0], s[mt][nt][1], s[mt][nt][2], s[mt][nt][3],
                            a[mt][0], a[mt][1], a[mt][2], a[mt][3],
                            bfr[nt][0], bfr[nt][1]);
        }

        const float scale = 0.125f;
#pragma unroll
        for (int mt = 0; mt < 3; mt++) {
#pragma unroll
            for (int nt = 0; nt < 4; nt++) {
                int qi0 = wnQ + nt * 8 + 2 * t4;
#pragma unroll
                for (int half = 0; half < 2; half++) {
                    int j = (wid >> 1) * 48 + mt * 16 + g + half * 8;
                    int t = k0 + j;
                    bool tin = (t >= 0) && (t < Nn);
                    float v0 = s[mt][nt][2 * half + 0];
                    float v1 = s[mt][nt][2 * half + 1];
                    bool ok0 = (j >= qi0) && (j <= qi0 + 2 * HALFW) && tin;
                    bool ok1 = (j >= qi0 + 1) && (j <= qi0 + 1 + 2 * HALFW) && tin;
                    St[j * AST_STR + qi0]     = ok0 ? v0 * scale : -1e30f;
                    St[j * AST_STR + qi0 + 1] = ok1 ? v1 * scale : -1e30f;
                }
            }
        }
    }
    __syncthreads();

    // --- softmax per qi column; write P fp16 (row-major [qi][j]) ---
#pragma unroll
    for (int i = 0; i < 8; i++) {
        int qi = wid * 8 + i;
        float v[6];
#pragma unroll
        for (int jj = 0; jj < 6; jj++)
            v[jj] = St[(lane + 32 * jj) * AST_STR + qi];
        float m = v[0];
#pragma unroll
        for (int jj = 1; jj < 6; jj++) m = fmaxf(m, v[jj]);
#pragma unroll
        for (int o = 16; o > 0; o >>= 1) m = fmaxf(m, __shfl_xor_sync(0xffffffffu, m, o));
        float e[6], ssum = 0.f;
#pragma unroll
        for (int jj = 0; jj < 6; jj++) { e[jj] = __expf(v[jj] - m); ssum += e[jj]; }
#pragma unroll
        for (int o = 16; o > 0; o >>= 1) ssum += __shfl_xor_sync(0xffffffffu, ssum, o);
        float inv = 1.f / ssum;
#pragma unroll
        for (int jj = 0; jj < 6; jj++)
            Pp[qi * 200 + lane + 32 * jj] = __float2half_rn(e[jj] * inv);
    }
    __syncthreads();

    // --- PV: O[qi][d] = P·V ; warp grid 4(qi) x 2(d) ---
    {
        const int wm = (wid >> 1) * 16;
        const int wn = (wid & 1) * 32;
        const uint32_t* Pu = (const uint32_t*)Pp;
        float o[4][4];
#pragma unroll
        for (int i = 0; i < 4; i++)
#pragma unroll
            for (int q = 0; q < 4; q++) o[i][q] = 0.f;

#pragma unroll 3
        for (int ks = 0; ks < 12; ks++) {     // j = 192 halves, 12 k16-steps
            const int kk = ks * 16;
            const int kw = ks * 8;
            uint32_t a[4];
            int r = wm + g;
            a[0] = Pu[r * PSW + t4 + kw];
            a[1] = Pu[(r + 8) * PSW + t4 + kw];
            a[2] = Pu[r * PSW + t4 + 4 + kw];
            a[3] = Pu[(r + 8) * PSW + t4 + 4 + kw];
#pragma unroll
            for (int nt = 0; nt < 4; nt++) {
                int cn = wn + nt * 8 + g;
                uint32_t lo0 = *(const unsigned short*)(Vs + (kk + 2 * t4) * 72 + cn);
                uint32_t hi0 = *(const unsigned short*)(Vs + (kk + 2 * t4 + 1) * 72 + cn);
                uint32_t lo1 = *(const unsigned short*)(Vs + (kk + 8 + 2 * t4) * 72 + cn);
                uint32_t hi1 = *(const unsigned short*)(Vs + (kk + 9 + 2 * t4) * 72 + cn);
                uint32_t b0 = lo0 | (hi0 << 16);
                uint32_t b1 = lo1 | (hi1 << 16);
                MMA_F16(o[nt][0], o[nt][1], o[nt][2], o[nt][3],
                        a[0], a[1], a[2], a[3], b0, b1);
            }
        }

#pragma unroll
        for (int nt = 0; nt < 4; nt++) {
            int d = wn + nt * 8 + 2 * t4;
#pragma unroll
            for (int half = 0; half < 2; half++) {
                int qi = wm + g + half * 8;
                *(__half2*)(out + (size_t)(b * Nn + q0 + qi) * Dd + h * 64 + d) =
                    __floats2half2_rn(o[nt][2 * half + 0], o[nt][2 * half + 1]);
            }
        }
    }
}

// ---------------------------------------------------------------------------
extern "C" void kernel_launch(void* const* d_in, const int* in_sizes, int n_in,
                              void* d_out, int out_size)
{
    const float* x    = (const float*)d_in[0];
    const float* Wqkv = (const float*)d_in[1];
    const float* bqkv = (const float*)d_in[2];
    const float* Wout = (const float*)d_in[3];
    const float* bout = (const float*)d_in[4];
    float* out = (float*)d_out;

    __half *qkv, *att, *xh, *W1t, *W2t;
    cudaGetSymbolAddress((void**)&qkv, g_qkv);
    cudaGetSymbolAddress((void**)&att, g_att);
    cudaGetSymbolAddress((void**)&xh,  g_xh);
    cudaGetSymbolAddress((void**)&W1t, g_W1t);
    cudaGetSymbolAddress((void**)&W2t, g_W2t);

    // Pre-passes: fp16 conversion + weight transpose
    {
        int n4 = Mrows * Dd / 4;
        cvt_f16_kernel<<<(n4 + 255) / 256, 256>>>(x, xh, n4);
        transpose_cvt_kernel<<<dim3(QKV_COLS / 32, Dd / 32), dim3(32, 8)>>>(Wqkv, W1t, Dd, QKV_COLS);
        transpose_cvt_kernel<<<dim3(Dd / 32, Dd / 32), dim3(32, 8)>>>(Wout, W2t, Dd, Dd);
    }

    // 1) QKV projection (fp16 tensor) -> fp16 qkv
    {
        cudaFuncSetAttribute((const void*)f16_mma_gemm<true>,
                             cudaFuncAttributeMaxDynamicSharedMemorySize, GEMM_SMEM);
        dim3 grid(QKV_COLS / BN, Mrows / BM);
        f16_mma_gemm<true><<<grid, GTHREADS, GEMM_SMEM>>>(
            xh, W1t, bqkv, qkv, Mrows, QKV_COLS, Dd);
    }

    // 2) Banded local attention (fp16 tensor) -> fp16 att
    {
        cudaFuncSetAttribute(local_attn_f16,
                             cudaFuncAttributeMaxDynamicSharedMemorySize, ATT_SMEM);
        dim3 grid(Nn / 64, Bb * Hh);
        local_attn_f16<<<grid, 256, ATT_SMEM>>>(qkv, att);
    }

    // 3) Output projection (fp16 tensor) -> fp32 out
    {
        cudaFuncSetAttribute((const void*)f16_mma_gemm<false>,
                             cudaFuncAttributeMaxDynamicSharedMemorySize, GEMM_SMEM);
        dim3 grid(Dd / BN, Mrows / BM);
        f16_mma_gemm<false><<<grid, GTHREADS, GEMM_SMEM>>>(
            att, W2t, bout, out, Mrows, Dd, Dd);
    }
}

// round 14
// speedup vs baseline: 2.3783x; 1.0722x over previous
#include <cuda_runtime.h>
#include <cuda_fp16.h>
#include <cstdint>

// Problem constants
#define Bb   2
#define Nn   2048
#define Dd   1024
#define Hh   16
#define HALFW 64
#define QKV_COLS (3*Dd)   // 3072
#define Mrows (Bb*Nn)     // 4096

// Scratch (device globals; no allocation allowed)
__device__ __half g_qkv[(size_t)Mrows*QKV_COLS];
__device__ __half g_att[(size_t)Mrows*Dd];
__device__ __half g_xh [(size_t)Mrows*Dd];
__device__ __half g_W1t[(size_t)QKV_COLS*Dd];
__device__ __half g_W2t[(size_t)Dd*Dd];

// ---------------------------------------------------------------------------
__device__ __forceinline__ uint32_t smem_u32(const void* p) {
    uint32_t a;
    asm("{ .reg .u64 t; cvta.to.shared.u64 t, %1; cvt.u32.u64 %0, t; }"
        : "=r"(a) : "l"(p));
    return a;
}
#define MMA_F16(d0,d1,d2,d3, a0,a1,a2,a3, b0,b1) \
    asm volatile( \
        "mma.sync.aligned.m16n8k16.row.col.f32.f16.f16.f32 " \
        "{%0,%1,%2,%3}, {%4,%5,%6,%7}, {%8,%9}, {%0,%1,%2,%3};" \
        : "+f"(d0), "+f"(d1), "+f"(d2), "+f"(d3) \
        : "r"(a0), "r"(a1), "r"(a2), "r"(a3), "r"(b0), "r"(b1))

__device__ __forceinline__ void ldsm_x4(uint32_t& r0, uint32_t& r1,
                                        uint32_t& r2, uint32_t& r3, uint32_t addr) {
    asm volatile("ldmatrix.sync.aligned.m8n8.x4.shared.b16 {%0,%1,%2,%3}, [%4];"
                 : "=r"(r0), "=r"(r1), "=r"(r2), "=r"(r3) : "r"(addr));
}
__device__ __forceinline__ void ldsm_x4_t(uint32_t& r0, uint32_t& r1,
                                          uint32_t& r2, uint32_t& r3, uint32_t addr) {
    asm volatile("ldmatrix.sync.aligned.m8n8.x4.trans.shared.b16 {%0,%1,%2,%3}, [%4];"
                 : "=r"(r0), "=r"(r1), "=r"(r2), "=r"(r3) : "r"(addr));
}

// ---------------------------------------------------------------------------
// fp16 mma.sync GEMM with ldmatrix fragment loads.
// A: [M][K] fp16. Bt: [N][K] fp16. BM=BN=128, BK=64h, 3-stage cp.async,
// 128 threads (4 warps, 64x64 tiles). Rows 144B (36 words, ≡4 mod 32).
// ---------------------------------------------------------------------------
#define BM 128
#define BN 128
#define BKH 64
#define STAGES 3
#define ROWB 144
#define STAGE_BYTES (2*BM*ROWB)               // 36864
#define GEMM_SMEM (STAGES*STAGE_BYTES)        // 110592
#define GTHREADS 128

__device__ __forceinline__ void g_load_stage(uint32_t sbase,
                                             const __half* __restrict__ A,
                                             const __half* __restrict__ Bt,
                                             int m0, int n0, int k0,
                                             int K, int tid)
{
#pragma unroll
    for (int i = 0; i < 8; i++) {
        int c  = tid + i * GTHREADS;
        int row = c >> 3, ch = c & 7;
        uint32_t dst = sbase + (uint32_t)(row * ROWB + ch * 16);
        const __half* src = A + (size_t)(m0 + row) * K + k0 + ch * 8;
        asm volatile("cp.async.cg.shared.global [%0], [%1], 16;" :: "r"(dst), "l"(src));
    }
    uint32_t bb = sbase + (uint32_t)(BM * ROWB);
#pragma unroll
    for (int i = 0; i < 8; i++) {
        int c  = tid + i * GTHREADS;
        int row = c >> 3, ch = c & 7;
        uint32_t dst = bb + (uint32_t)(row * ROWB + ch * 16);
        const __half* src = Bt + (size_t)(n0 + row) * K + k0 + ch * 8;
        asm volatile("cp.async.cg.shared.global [%0], [%1], 16;" :: "r"(dst), "l"(src));
    }
    asm volatile("cp.async.commit_group;" ::: "memory");
}

template<bool HALF_OUT>
__global__ __launch_bounds__(GTHREADS, 2)
void f16_mma_gemm(const __half* __restrict__ A, const __half* __restrict__ Bt,
                  const float* __restrict__ bias, void* __restrict__ Cv,
                  int M, int N, int K)
{
    extern __shared__ char smc[];
    const int tid  = threadIdx.x;
    const int wid  = tid >> 5;
    const int lane = tid & 31;
    const int g    = lane >> 2;
    const int t4   = lane & 3;
    const int m0 = blockIdx.y * BM;
    const int n0 = blockIdx.x * BN;
    const int wm = (wid >> 1) * 64;
    const int wn = (wid & 1) * 64;
    const uint32_t smb = smem_u32(smc);

    // ldmatrix lane-address components
    const int l7  = lane & 7;
    const int l8  = (lane >> 3) & 1;
    const int l16 = lane >> 4;

    float acc[4][8][4];
#pragma unroll
    for (int i = 0; i < 4; i++)
#pragma unroll
        for (int j = 0; j < 8; j++)
#pragma unroll
            for (int q = 0; q < 4; q++) acc[i][j][q] = 0.f;

    const int NITER = K / BKH;
#pragma unroll
    for (int s = 0; s < STAGES - 1; s++)
        g_load_stage(smb + (uint32_t)(s * STAGE_BYTES), A, Bt, m0, n0, s * BKH, K, tid);

    for (int it = 0; it < NITER; it++) {
        asm volatile("cp.async.wait_group %0;" :: "n"(STAGES - 2) : "memory");
        __syncthreads();

        if (it + STAGES - 1 < NITER) {
            int ps = (it + STAGES - 1) % STAGES;
            g_load_stage(smb + (uint32_t)(ps * STAGE_BYTES), A, Bt,
                         m0, n0, (it + STAGES - 1) * BKH, K, tid);
        }

        const uint32_t stA = smb + (uint32_t)((it % STAGES) * STAGE_BYTES);
        const uint32_t stB = stA + BM * ROWB;
        // A x4: mats (rows 0-7,k0-7)(rows 8-15,k0-7)(rows 0-7,k8-15)(rows 8-15,k8-15)
        const uint32_t aBase = stA + (uint32_t)((wm + l7 + l8 * 8) * ROWB) + l16 * 16;
        // B x4: mats (n 0-7,k0-7)(n 0-7,k8-15)(n 8-15,k0-7)(n 8-15,k8-15)
        const uint32_t bBase = stB + (uint32_t)((wn + l7 + l16 * 8) * ROWB) + l8 * 16;

#pragma unroll
        for (int ks = 0; ks < 4; ks++) {
            const uint32_t koff = ks * 32;    // 16 halves per k16 step
            uint32_t a[4][4];
#pragma unroll
            for (int mt = 0; mt < 4; mt++)
                ldsm_x4(a[mt][0], a[mt][1], a[mt][2], a[mt][3],
                        aBase + mt * 16 * ROWB + koff);
#pragma unroll
            for (int p = 0; p < 4; p++) {
                uint32_t b0, b1, b2, b3;
                ldsm_x4(b0, b1, b2, b3, bBase + p * 16 * ROWB + koff);
#pragma unroll
                for (int mt = 0; mt < 4; mt++) {
                    MMA_F16(acc[mt][2*p][0], acc[mt][2*p][1], acc[mt][2*p][2], acc[mt][2*p][3],
                            a[mt][0], a[mt][1], a[mt][2], a[mt][3], b0, b1);
                    MMA_F16(acc[mt][2*p+1][0], acc[mt][2*p+1][1], acc[mt][2*p+1][2], acc[mt][2*p+1][3],
                            a[mt][0], a[mt][1], a[mt][2], a[mt][3], b2, b3);
                }
            }
        }
    }

#pragma unroll
    for (int nt = 0; nt < 8; nt++) {
        int cc = n0 + wn + nt * 8 + 2 * t4;
        float2 bv = *(const float2*)(bias + cc);
#pragma unroll
        for (int mt = 0; mt < 4; mt++) {
            int r0 = m0 + wm + mt * 16 + g;
            float2 o0, o1;
            o0.x = acc[mt][nt][0] + bv.x;  o0.y = acc[mt][nt][1] + bv.y;
            o1.x = acc[mt][nt][2] + bv.x;  o1.y = acc[mt][nt][3] + bv.y;
            if (HALF_OUT) {
                __half* Ch = (__half*)Cv;
                *(__half2*)(Ch + (size_t)r0 * N + cc)       = __floats2half2_rn(o0.x, o0.y);
                *(__half2*)(Ch + (size_t)(r0 + 8) * N + cc) = __floats2half2_rn(o1.x, o1.y);
            } else {
                float* Cf = (float*)Cv;
                *(float2*)(Cf + (size_t)r0 * N + cc)       = o0;
                *(float2*)(Cf + (size_t)(r0 + 8) * N + cc) = o1;
            }
        }
    }
}

// ---------------------------------------------------------------------------
// Pre-passes
// ---------------------------------------------------------------------------
__global__ void cvt_f16_kernel(const float* __restrict__ in, __half* __restrict__ out, int n4)
{
    int i = blockIdx.x * blockDim.x + threadIdx.x;
    if (i < n4) {
        float4 v = ((const float4*)in)[i];
        __half2 h0 = __floats2half2_rn(v.x, v.y);
        __half2 h1 = __floats2half2_rn(v.z, v.w);
        uint2 u;
        u.x = *(uint32_t*)&h0;
        u.y = *(uint32_t*)&h1;
        ((uint2*)out)[i] = u;
    }
}

__global__ void transpose_cvt_kernel(const float* __restrict__ W, __half* __restrict__ WT,
                                     int K, int N)
{
    __shared__ float t[32][33];
    int x = blockIdx.x * 32 + threadIdx.x;
#pragma unroll
    for (int j = 0; j < 4; j++) {
        int y = blockIdx.y * 32 + threadIdx.y + j * 8;
        t[threadIdx.y + j * 8][threadIdx.x] = W[(size_t)y * N + x];
    }
    __syncthreads();
    int x2 = blockIdx.y * 32 + threadIdx.x;
#pragma unroll
    for (int j = 0; j < 4; j++) {
        int y2 = blockIdx.x * 32 + threadIdx.y + j * 8;
        WT[(size_t)y2 * K + x2] = __float2half_rn(t[threadIdx.x][threadIdx.y + j * 8]);
    }
}

// ---------------------------------------------------------------------------
// fp16 tensor-core local attention with ldmatrix fragment loads.
// ---------------------------------------------------------------------------
#define AQ_OFF 0
#define AK_OFF 9216
#define AV_OFF (AK_OFF + 192*144)         // 36864
#define AST_OFF (AV_OFF + 192*144)        // 64512
#define AP_OFF AK_OFF
#define AST_STR 65
#define PROWB 400                         // P row bytes (200 halves)
#define ATT_SMEM (AST_OFF + 192*AST_STR*4)   // 114432

__global__ __launch_bounds__(256, 2)
void local_attn_f16(const __half* __restrict__ qkv, __half* __restrict__ out)
{
    extern __shared__ char smc[];
    float*  St = (float*)(smc + AST_OFF);
    __half* Pp = (__half*)(smc + AP_OFF);

    const int tid  = threadIdx.x;
    const int wid  = tid >> 5;
    const int lane = tid & 31;
    const int g    = lane >> 2;
    const int t4   = lane & 3;
    const int l7  = lane & 7;
    const int l8  = (lane >> 3) & 1;
    const int l16 = lane >> 4;
    const int bh = blockIdx.y;
    const int b  = bh / Hh;
    const int h  = bh % Hh;
    const int q0 = blockIdx.x * 64;
    const int k0 = q0 - HALFW;
    const __half* base = qkv + (size_t)b * Nn * QKV_COLS + h * 64;
    const uint32_t smb = smem_u32(smc);

    // --- K,V via cp.async (zero-fill OOB) ---
#pragma unroll
    for (int i = 0; i < 6; i++) {
        int c   = tid + i * 256;
        int row = c >> 3, ch = c & 7;
        int t   = k0 + row;
        int tc  = t < 0 ? 0 : (t >= Nn ? Nn - 1 : t);
        int sz  = (t >= 0 && t < Nn) ? 16 : 0;
        const __half* srck = base + (size_t)tc * QKV_COLS + Dd + ch * 8;
        const __half* srcv = srck + Dd;
        uint32_t dk = smb + (uint32_t)(AK_OFF + row * 144 + ch * 16);
        uint32_t dv = smb + (uint32_t)(AV_OFF + row * 144 + ch * 16);
        asm volatile("cp.async.cg.shared.global [%0], [%1], 16, %2;"
                     :: "r"(dk), "l"(srck), "r"(sz));
        asm volatile("cp.async.cg.shared.global [%0], [%1], 16, %2;"
                     :: "r"(dv), "l"(srcv), "r"(sz));
    }
#pragma unroll
    for (int i = 0; i < 2; i++) {
        int c   = tid + i * 256;
        int row = c >> 3, ch = c & 7;
        const __half* src = base + (size_t)(q0 + row) * QKV_COLS + ch * 8;
        uint32_t dq = smb + (uint32_t)(AQ_OFF + row * 144 + ch * 16);
        asm volatile("cp.async.cg.shared.global [%0], [%1], 16;" :: "r"(dq), "l"(src));
    }
    asm volatile("cp.async.commit_group;" ::: "memory");
    asm volatile("cp.async.wait_group 0;" ::: "memory");
    __syncthreads();

    // --- scores (transposed): St[j][qi] = K·Q^T ; warp grid 4(j) x 2(qi) ---
    {
        const int wmJ = (wid >> 1) * 48;
        const int wnQ = (wid & 1) * 32;
        const uint32_t aBase = smb + (uint32_t)(AK_OFF + (wmJ + l7 + l8 * 8) * 144) + l16 * 16;
        const uint32_t bBase = smb + (uint32_t)(AQ_OFF + (wnQ + l7 + l16 * 8) * 144) + l8 * 16;
        float s[3][4][4];
#pragma unroll
        for (int i = 0; i < 3; i++)
#pragma unroll
            for (int j = 0; j < 4; j++)
#pragma unroll
                for (int q = 0; q < 4; q++) s[i][j][q] = 0.f;

#pragma unroll
        for (int ks = 0; ks < 4; ks++) {
            const uint32_t koff = ks * 32;
            uint32_t a[3][4];
#pragma unroll
            for (int mt = 0; mt < 3; mt++)
                ldsm_x4(a[mt][0], a[mt][1], a[mt][2], a[mt][3],
                        aBase + mt * 16 * 144 + koff);
#pragma unroll
            for (int p = 0; p < 2; p++) {
                uint32_t b0, b1, b2, b3;
                ldsm_x4(b0, b1, b2, b3, bBase + p * 16 * 144 + koff);
#pragma unroll
                for (int mt = 0; mt < 3; mt++) {
                    MMA_F16(s[mt][2*p][0], s[mt][2*p][1], s[mt][2*p][2], s[mt][2*p][3],
                            a[mt][0], a[mt][1], a[mt][2], a[mt][3], b0, b1);
                    MMA_F16(s[mt][2*p+1][0], s[mt][2*p+1][1], s[mt][2*p+1][2], s[mt][2*p+1][3],
                            a[mt][0], a[mt][1], a[mt][2], a[mt][3], b2, b3);
                }
            }
        }

        const float scale = 0.125f;
#pragma unroll
        for (int mt = 0; mt < 3; mt++) {
#pragma unroll
            for (int nt = 0; nt < 4; nt++) {
                int qi0 = wnQ + nt * 8 + 2 * t4;
#pragma unroll
                for (int half = 0; half < 2; half++) {
                    int j = wmJ + mt * 16 + g + half * 8;
                    int t = k0 + j;
                    bool tin = (t >= 0) && (t < Nn);
                    float v0 = s[mt][nt][2 * half + 0];
                    float v1 = s[mt][nt][2 * half + 1];
                    bool ok0 = (j >= qi0) && (j <= qi0 + 2 * HALFW) && tin;
                    bool ok1 = (j >= qi0 + 1) && (j <= qi0 + 1 + 2 * HALFW) && tin;
                    St[j * AST_STR + qi0]     = ok0 ? v0 * scale : -1e30f;
                    St[j * AST_STR + qi0 + 1] = ok1 ? v1 * scale : -1e30f;
                }
            }
        }
    }
    __syncthreads();

    // --- softmax per qi column; write P fp16 row-major [qi][200h] ---
#pragma unroll
    for (int i = 0; i < 8; i++) {
        int qi = wid * 8 + i;
        float v[6];
#pragma unroll
        for (int jj = 0; jj < 6; jj++)
            v[jj] = St[(lane + 32 * jj) * AST_STR + qi];
        float m = v[0];
#pragma unroll
        for (int jj = 1; jj < 6; jj++) m = fmaxf(m, v[jj]);
#pragma unroll
        for (int o = 16; o > 0; o >>= 1) m = fmaxf(m, __shfl_xor_sync(0xffffffffu, m, o));
        float e[6], ssum = 0.f;
#pragma unroll
        for (int jj = 0; jj < 6; jj++) { e[jj] = __expf(v[jj] - m); ssum += e[jj]; }
#pragma unroll
        for (int o = 16; o > 0; o >>= 1) ssum += __shfl_xor_sync(0xffffffffu, ssum, o);
        float inv = 1.f / ssum;
#pragma unroll
        for (int jj = 0; jj < 6; jj++)
            Pp[qi * 200 + lane + 32 * jj] = __float2half_rn(e[jj] * inv);
    }
    __syncthreads();

    // --- PV: O[qi][d] = P·V ; warp grid 4(qi) x 2(d) ---
    {
        const int wm = (wid >> 1) * 16;
        const int wn = (wid & 1) * 32;
        const uint32_t aBase = smb + (uint32_t)(AP_OFF + (wm + l7 + l8 * 8) * PROWB) + l16 * 16;
        const uint32_t vBase = smb + (uint32_t)(AV_OFF + (l7 + l8 * 8) * 144
                                                + (wn + l16 * 8) * 2);
        float o[4][4];
#pragma unroll
        for (int i = 0; i < 4; i++)
#pragma unroll
            for (int q = 0; q < 4; q++) o[i][q] = 0.f;

#pragma unroll 3
        for (int ks = 0; ks < 12; ks++) {
            uint32_t a0, a1, a2, a3;
            ldsm_x4(a0, a1, a2, a3, aBase + ks * 32);
#pragma unroll
            for (int p = 0; p < 2; p++) {
                uint32_t b0, b1, b2, b3;
                ldsm_x4_t(b0, b1, b2, b3, vBase + ks * 16 * 144 + p * 32);
                MMA_F16(o[2*p][0], o[2*p][1], o[2*p][2], o[2*p][3],
                        a0, a1, a2, a3, b0, b1);
                MMA_F16(o[2*p+1][0], o[2*p+1][1], o[2*p+1][2], o[2*p+1][3],
                        a0, a1, a2, a3, b2, b3);
            }
        }

#pragma unroll
        for (int nt = 0; nt < 4; nt++) {
            int d = wn + nt * 8 + 2 * t4;
#pragma unroll
            for (int half = 0; half < 2; half++) {
                int qi = wm + g + half * 8;
                *(__half2*)(out + (size_t)(b * Nn + q0 + qi) * Dd + h * 64 + d) =
                    __floats2half2_rn(o[nt][2 * half + 0], o[nt][2 * half + 1]);
            }
        }
    }
}

// ---------------------------------------------------------------------------
extern "C" void kernel_launch(void* const* d_in, const int* in_sizes, int n_in,
                              void* d_out, int out_size)
{
    const float* x    = (const float*)d_in[0];
    const float* Wqkv = (const float*)d_in[1];
    const float* bqkv = (const float*)d_in[2];
    const float* Wout = (const float*)d_in[3];
    const float* bout = (const float*)d_in[4];
    float* out = (float*)d_out;

    __half *qkv, *att, *xh, *W1t, *W2t;
    cudaGetSymbolAddress((void**)&qkv, g_qkv);
    cudaGetSymbolAddress((void**)&att, g_att);
    cudaGetSymbolAddress((void**)&xh,  g_xh);
    cudaGetSymbolAddress((void**)&W1t, g_W1t);
    cudaGetSymbolAddress((void**)&W2t, g_W2t);

    // Pre-passes
    {
        int n4 = Mrows * Dd / 4;
        cvt_f16_kernel<<<(n4 + 255) / 256, 256>>>(x, xh, n4);
        transpose_cvt_kernel<<<dim3(QKV_COLS / 32, Dd / 32), dim3(32, 8)>>>(Wqkv, W1t, Dd, QKV_COLS);
        transpose_cvt_kernel<<<dim3(Dd / 32, Dd / 32), dim3(32, 8)>>>(Wout, W2t, Dd, Dd);
    }

    // 1) QKV projection (fp16 tensor) -> fp16 qkv
    {
        cudaFuncSetAttribute((const void*)f16_mma_gemm<true>,
                             cudaFuncAttributeMaxDynamicSharedMemorySize, GEMM_SMEM);
        dim3 grid(QKV_COLS / BN, Mrows / BM);
        f16_mma_gemm<true><<<grid, GTHREADS, GEMM_SMEM>>>(
            xh, W1t, bqkv, qkv, Mrows, QKV_COLS, Dd);
    }

    // 2) Banded local attention (fp16 tensor) -> fp16 att
    {
        cudaFuncSetAttribute(local_attn_f16,
                             cudaFuncAttributeMaxDynamicSharedMemorySize, ATT_SMEM);
        dim3 grid(Nn / 64, Bb * Hh);
        local_attn_f16<<<grid, 256, ATT_SMEM>>>(qkv, att);
    }

    // 3) Output projection (fp16 tensor) -> fp32 out
    {
        cudaFuncSetAttribute((const void*)f16_mma_gemm<false>,
                             cudaFuncAttributeMaxDynamicSharedMemorySize, GEMM_SMEM);
        dim3 grid(Dd / BN, Mrows / BM);
        f16_mma_gemm<false><<<grid, GTHREADS, GEMM_SMEM>>>(
            att, W2t, bout, out, Mrows, Dd, Dd);
    }
}